// round 17
// baseline (speedup 1.0000x reference)
#include <cuda_runtime.h>
#include <cuda_fp16.h>
#include <math.h>
#include <cstdint>

#define NBLK 32
#define CAP 1024
#define DK 256
#define DH 768
#define NQ 8192
#define NPART 32   /* one memory block per CTA */

typedef uint32_t u32;

// scratch (device globals: no allocation allowed)
__device__ __half g_qh[NQ * DK];              // layernormed queries * 1/16, fp16
__device__ __half g_kh[NBLK * CAP * DK];      // keys, fp16
__device__ __half g_vth[NBLK * DK * CAP];     // values transposed [b][d][key], fp16
__device__ __half g_hsh[NQ * DH];             // hidden states, fp16
__device__ __half g_wkth[DK * DH];            // Wk^T  [256][768], fp16
__device__ __half g_woth[DH * DK];            // Wo^T  [768][256], fp16
__device__ __half g_r[NPART * NQ * DK];       // per-block retrieved partials, fp16
__device__ __half g_rsh[NQ * DK];             // reduced retrieved values, fp16

__device__ __forceinline__ u32 packh2(float a, float b) {
    __half2 h = __floats2half2_rn(a, b);
    return *(u32*)&h;
}

// fp16 tensor-core mma, fp32 accumulate
__device__ __forceinline__ void mma_f16(float* d,
    u32 a0, u32 a1, u32 a2, u32 a3, u32 b0, u32 b1)
{
    asm("mma.sync.aligned.m16n8k16.row.col.f32.f16.f16.f32 "
        "{%0,%1,%2,%3},{%4,%5,%6,%7},{%8,%9},{%0,%1,%2,%3};"
        : "+f"(d[0]), "+f"(d[1]), "+f"(d[2]), "+f"(d[3])
        : "r"(a0), "r"(a1), "r"(a2), "r"(a3), "r"(b0), "r"(b1));
}

__device__ __forceinline__ u32 s2u(const void* p) {
    u32 a;
    asm("{ .reg .u64 t; cvta.to.shared.u64 t, %1; cvt.u32.u64 %0, t; }"
        : "=r"(a) : "l"(p));
    return a;
}
__device__ __forceinline__ void cpa16(u32 dst, const void* src) {
    asm volatile("cp.async.cg.shared.global [%0], [%1], 16;"
                 :: "r"(dst), "l"(src) : "memory");
}
#define CPA_COMMIT() asm volatile("cp.async.commit_group;" ::: "memory")
#define CPA_WAIT1()  asm volatile("cp.async.wait_group 1;" ::: "memory")

#define LDSM4(r, a) asm volatile( \
    "ldmatrix.sync.aligned.m8n8.x4.shared.b16 {%0,%1,%2,%3}, [%4];" \
    : "=r"((r)[0]), "=r"((r)[1]), "=r"((r)[2]), "=r"((r)[3]) : "r"(a))

// ---------------------------------------------------------------------------
// Kernel P (fused prep), roles by blockIdx.x:
//  keys->fp16 | V transpose->fp16 [b][d][key] | hs->fp16 | Wk^T | Wo^T
// ---------------------------------------------------------------------------
#define KH_BLOCKS  ((NBLK * CAP * DK) / (256 * 8))   /* 4096 */
#define VTH_BLOCKS ((DK / 32) * (CAP / 32) * NBLK)   /* 8192 */
#define HS_BLOCKS  ((NQ * DH) / (256 * 8))           /* 3072 */
#define WKT_BLOCKS ((DH / 32) * (DK / 32))           /* 192  */
#define WOT_BLOCKS ((DK / 32) * (DH / 32))           /* 192  */
#define PREP_GRID (KH_BLOCKS + VTH_BLOCKS + HS_BLOCKS + WKT_BLOCKS + WOT_BLOCKS)

__device__ __forceinline__ void tile_transpose(
    const float* __restrict__ in, __half* __restrict__ out,
    int R, int C, int rt, int ct, float t[32][33])
{
    const int r = threadIdx.x >> 3, c4 = (threadIdx.x & 7) * 4;
    float4 v = *(const float4*)(in + (size_t)(rt * 32 + r) * C + ct * 32 + c4);
    t[r][c4] = v.x; t[r][c4 + 1] = v.y; t[r][c4 + 2] = v.z; t[r][c4 + 3] = v.w;
    __syncthreads();
    uint2 o = make_uint2(packh2(t[c4][r], t[c4 + 1][r]),
                         packh2(t[c4 + 2][r], t[c4 + 3][r]));
    *(uint2*)(out + (size_t)(ct * 32 + r) * R + rt * 32 + c4) = o;
}

__global__ __launch_bounds__(256) void prep_kernel(
    const float* __restrict__ mk, const float* __restrict__ mv,
    const float* __restrict__ hs, const float* __restrict__ Wk,
    const float* __restrict__ Wo)
{
    __shared__ float t[32][33];
    int bx = blockIdx.x;
    if (bx < KH_BLOCKS) {
        size_t i = ((size_t)bx * 256 + threadIdx.x) * 8;
        float4 v0 = *(const float4*)(mk + i);
        float4 v1 = *(const float4*)(mk + i + 4);
        *(uint4*)(g_kh + i) = make_uint4(packh2(v0.x, v0.y), packh2(v0.z, v0.w),
                                         packh2(v1.x, v1.y), packh2(v1.z, v1.w));
        return;
    }
    bx -= KH_BLOCKS;
    if (bx < VTH_BLOCKS) {
        const int dt = bx & 7, kt = (bx >> 3) & 31, b = bx >> 8;
        tile_transpose(mv + (size_t)b * CAP * DK, g_vth + (size_t)b * DK * CAP,
                       CAP, DK, kt, dt, t);
        return;
    }
    bx -= VTH_BLOCKS;
    if (bx < HS_BLOCKS) {
        size_t i = ((size_t)bx * 256 + threadIdx.x) * 8;
        float4 v0 = *(const float4*)(hs + i);
        float4 v1 = *(const float4*)(hs + i + 4);
        *(uint4*)(g_hsh + i) = make_uint4(packh2(v0.x, v0.y), packh2(v0.z, v0.w),
                                          packh2(v1.x, v1.y), packh2(v1.z, v1.w));
        return;
    }
    bx -= HS_BLOCKS;
    if (bx < WKT_BLOCKS) {
        const int ct = bx & 7, rt = bx >> 3;   // Wk: R=768, C=256
        tile_transpose(Wk, g_wkth, DH, DK, rt, ct, t);
        return;
    }
    bx -= WKT_BLOCKS;
    {
        const int ct = bx % 24, rt = bx / 24;  // Wo: R=256, C=768
        tile_transpose(Wo, g_woth, DK, DH, rt, ct, t);
    }
}

// ---------------------------------------------------------------------------
// Kernel A: q = LayerNorm(hsh @ WkT + bk) * ln_w + ln_b, scaled 1/16 -> fp16
// fp16 tensor-core GEMM, BM=32 (256 CTAs), TWO CTAs per SM.
// 8 warps: mw=w>>2 -> m16 tile (2), nh=w&3 -> n64 group (4). acc 32 regs.
// LN via E[x^2]-mu^2; partials per (row, n64 group) in Lq[32][4][2].
// ---------------------------------------------------------------------------
#define QP_ASTR 136
#define QP_SMEM (1024 + 32 * QP_ASTR * 2 + 256 * QP_ASTR * 2)

extern __shared__ char qp_raw[];

__global__ void __launch_bounds__(256, 2) qproj_ln_kernel(
    const float* __restrict__ bk, const float* __restrict__ lnw,
    const float* __restrict__ lnb)
{
    float*  Lq = (float*)qp_raw;                 // [32][4 groups][2 {sum,sq}]
    __half* As = (__half*)(qp_raw + 1024);       // [32][136]
    __half* Bs = As + 32 * QP_ASTR;              // [256][136]

    const int tid = threadIdx.x;
    const int w = tid >> 5, lane = tid & 31;
    const int t4 = lane >> 2, tq = lane & 3;
    const int mw = w >> 2, nh = w & 3;
    const int m0 = blockIdx.x * 32;

    const int l15 = lane & 15, lh = lane >> 4;
    const u32 qa = s2u(As) + (u32)(((mw * 16 + l15) * QP_ASTR + lh * 8) * 2);
    const u32 qb = s2u(Bs) + (u32)(((nh * 64 + l15) * QP_ASTR + lh * 8) * 2);

    float acc[8][4];
#pragma unroll
    for (int nt = 0; nt < 8; nt++)
#pragma unroll
        for (int j = 0; j < 4; j++) acc[nt][j] = 0.f;

    for (int kc = 0; kc < DH / 128; kc++) {
        const int k0 = kc * 128;
#pragma unroll
        for (int u = 0; u < 2; u++) {   // A: 32 x 16 uint4
            int idx = tid + u * 256;
            int row = idx >> 4, seg = idx & 15;
            *(uint4*)(As + row * QP_ASTR + seg * 8) =
                *(const uint4*)(g_hsh + (size_t)(m0 + row) * DH + k0 + seg * 8);
        }
#pragma unroll
        for (int u = 0; u < 16; u++) {  // B: 256 x 16 uint4
            int idx = tid + u * 256;
            int row = idx >> 4, seg = idx & 15;
            *(uint4*)(Bs + row * QP_ASTR + seg * 8) =
                *(const uint4*)(g_wkth + (size_t)row * DH + k0 + seg * 8);
        }
        __syncthreads();
#pragma unroll
        for (int kk = 0; kk < 8; kk++) {
            u32 A[4];
            LDSM4(A, qa + kk * 32);
#pragma unroll
            for (int nt16 = 0; nt16 < 4; nt16++) {
                u32 B[4];
                LDSM4(B, qb + nt16 * 16 * QP_ASTR * 2 + kk * 32);
                mma_f16(acc[2 * nt16],     A[0], A[1], A[2], A[3], B[0], B[2]);
                mma_f16(acc[2 * nt16 + 1], A[0], A[1], A[2], A[3], B[1], B[3]);
            }
        }
        __syncthreads();
    }

    // bias + per-(row, group) sums / sumsq
    const int row = mw * 16 + t4;
    float slo = 0.f, sqlo = 0.f, shi = 0.f, sqhi = 0.f;
#pragma unroll
    for (int nt = 0; nt < 8; nt++) {
        int col = nh * 64 + nt * 8 + 2 * tq;
        float2 bkv = *(const float2*)(bk + col);
        acc[nt][0] += bkv.x; acc[nt][1] += bkv.y;
        acc[nt][2] += bkv.x; acc[nt][3] += bkv.y;
        slo += acc[nt][0] + acc[nt][1];
        sqlo += acc[nt][0] * acc[nt][0] + acc[nt][1] * acc[nt][1];
        shi += acc[nt][2] + acc[nt][3];
        sqhi += acc[nt][2] * acc[nt][2] + acc[nt][3] * acc[nt][3];
    }
#pragma unroll
    for (int o = 1; o <= 2; o <<= 1) {
        slo  += __shfl_xor_sync(0xffffffffu, slo, o);
        sqlo += __shfl_xor_sync(0xffffffffu, sqlo, o);
        shi  += __shfl_xor_sync(0xffffffffu, shi, o);
        sqhi += __shfl_xor_sync(0xffffffffu, sqhi, o);
    }
    if (tq == 0) {   // unique writer per (row, group)
        Lq[row * 8 + nh * 2]           = slo;
        Lq[row * 8 + nh * 2 + 1]       = sqlo;
        Lq[(row + 8) * 8 + nh * 2]     = shi;
        Lq[(row + 8) * 8 + nh * 2 + 1] = sqhi;
    }
    __syncthreads();

    float mu0, rs0, mu1, rs1;
    {
        float s = Lq[row * 8] + Lq[row * 8 + 2] + Lq[row * 8 + 4] + Lq[row * 8 + 6];
        float q = Lq[row * 8 + 1] + Lq[row * 8 + 3] + Lq[row * 8 + 5] + Lq[row * 8 + 7];
        mu0 = s * (1.0f / 256.0f);
        rs0 = rsqrtf(q * (1.0f / 256.0f) - mu0 * mu0 + 1e-5f);
        const int r8 = row + 8;
        s = Lq[r8 * 8] + Lq[r8 * 8 + 2] + Lq[r8 * 8 + 4] + Lq[r8 * 8 + 6];
        q = Lq[r8 * 8 + 1] + Lq[r8 * 8 + 3] + Lq[r8 * 8 + 5] + Lq[r8 * 8 + 7];
        mu1 = s * (1.0f / 256.0f);
        rs1 = rsqrtf(q * (1.0f / 256.0f) - mu1 * mu1 + 1e-5f);
    }
#pragma unroll
    for (int nt = 0; nt < 8; nt++) {
        int col = nh * 64 + nt * 8 + 2 * tq;
        float2 lw = *(const float2*)(lnw + col);
        float2 lb = *(const float2*)(lnb + col);
        float o0 = ((acc[nt][0] - mu0) * rs0 * lw.x + lb.x) * 0.0625f;
        float o1 = ((acc[nt][1] - mu0) * rs0 * lw.y + lb.y) * 0.0625f;
        float o2 = ((acc[nt][2] - mu1) * rs1 * lw.x + lb.x) * 0.0625f;
        float o3 = ((acc[nt][3] - mu1) * rs1 * lw.y + lb.y) * 0.0625f;
        *(u32*)(g_qh + (size_t)(m0 + row) * DK + col)     = packh2(o0, o1);
        *(u32*)(g_qh + (size_t)(m0 + row + 8) * DK + col) = packh2(o2, o3);
    }
}

// ---------------------------------------------------------------------------
// Kernel B: attention, ONE memory block per CTA (grid 128 x 32), chunk = 32
// keys, double-buffered cp.async, 256 threads, TWO CTAs per SM (R16 proven).
// ---------------------------------------------------------------------------
#define QSTR 264
#define KSTR 264
#define VSTR 40
#define PSTR 40
#define KBUF (32 * KSTR)
#define VBUF (256 * VSTR)
#define ATTN_SMEM (512 + 64*QSTR*2 + 2*KBUF*2 + 2*VBUF*2 + 64*PSTR*2)

extern __shared__ char sm_raw[];

__global__ void __launch_bounds__(256, 2) attn_kernel(const int* __restrict__ usage)
{
    float*  Ls  = (float*)sm_raw;                 // [64][2]
    __half* Qs  = (__half*)(sm_raw + 512);        // [64][264]
    __half* Ks  = Qs + 64 * QSTR;                 // 2 x [32][264]
    __half* Vts = Ks + 2 * KBUF;                  // 2 x [256][40]
    __half* Ps  = Vts + 2 * VBUF;                 // [64][40]

    const u32 ks_u = s2u(Ks);
    const u32 vt_u = s2u(Vts);

    const int tid  = threadIdx.x;
    const int w    = tid >> 5;
    const int lane = tid & 31;
    const int t4   = lane >> 2;
    const int tq   = lane & 3;
    const int q0   = blockIdx.x * 64;
    const int b    = blockIdx.y;

    const int mw = w >> 1;          // QK m16 tile
    const int nh = w & 1;           // QK key-half (n16)
    const int mg = w & 1;           // PV m32 group
    const int ng = w >> 1;          // PV n64 group

    const int l15 = lane & 15, lh = lane >> 4;
    const u32 qa  = s2u(Qs) + (u32)(((mw * 16 + l15) * QSTR + lh * 8) * 2);
    const u32 kb0 = (u32)(((nh * 16 + l15) * KSTR + lh * 8) * 2);   // + ks_u + buf
    const u32 pa0 = s2u(Ps) + (u32)(((mg * 32 + l15) * PSTR + lh * 8) * 2);
    const u32 pa1 = pa0 + 16 * PSTR * 2;
    const u32 vb0 = (u32)(((ng * 64 + l15) * VSTR + lh * 8) * 2);   // + vt_u + buf

    // Q tile -> smem
#pragma unroll
    for (int u = 0; u < 8; u++) {
        int idx = tid + u * 256;
        int row = idx >> 5, seg = idx & 31;
        uint4 v = *(const uint4*)(g_qh + ((size_t)(q0 + row) << 8) + seg * 8);
        *(uint4*)(Qs + row * QSTR + seg * 8) = v;
    }

    const int use = __ldg(usage + b);
    const int nch = (use + 31) >> 5;
    const __half* kgb = g_kh + (size_t)b * CAP * DK;
    const __half* vgb = g_vth + (size_t)b * DK * CAP;

    // prefetch chunk 0 into buffer 0
#pragma unroll
    for (int u = 0; u < 4; u++) {
        int idx = tid + u * 256;
        int key = idx >> 5, seg = idx & 31;
        cpa16(ks_u + (key * KSTR + seg * 8) * 2, kgb + (size_t)key * DK + seg * 8);
        int d = idx >> 2, sg = idx & 3;
        cpa16(vt_u + (d * VSTR + sg * 8) * 2, vgb + (size_t)d * CAP + sg * 8);
    }
    CPA_COMMIT();

    float acc[2][8][4];
#pragma unroll
    for (int mt = 0; mt < 2; mt++)
#pragma unroll
        for (int nt = 0; nt < 8; nt++)
#pragma unroll
            for (int j = 0; j < 4; j++) acc[mt][nt][j] = 0.f;

    for (int ch = 0; ch < nch; ch++) {
        const int buf = ch & 1;
        const int c0 = ch * 32;

        __syncthreads();   // A: prev chunk fully consumed -> buf^1 free

        if (ch + 1 < nch) {
            const int pb = buf ^ 1;
            const __half* kg = kgb + (size_t)(c0 + 32) * DK;
            const __half* vg = vgb + (c0 + 32);
            const u32 kd = ks_u + pb * KBUF * 2;
            const u32 vd = vt_u + pb * VBUF * 2;
#pragma unroll
            for (int u = 0; u < 4; u++) {
                int idx = tid + u * 256;
                int key = idx >> 5, seg = idx & 31;
                cpa16(kd + (key * KSTR + seg * 8) * 2, kg + (size_t)key * DK + seg * 8);
                int d = idx >> 2, sg = idx & 3;
                cpa16(vd + (d * VSTR + sg * 8) * 2, vg + (size_t)d * CAP + sg * 8);
            }
        }
        CPA_COMMIT();
        CPA_WAIT1();       // current chunk complete
        __syncthreads();   // B: chunk data visible

        // ---- S = Q K^T : m16 x n16 over k=256 ----
        const u32 kbase = ks_u + buf * KBUF * 2 + kb0;
        float s[2][4];
#pragma unroll
        for (int nt = 0; nt < 2; nt++)
#pragma unroll
            for (int j = 0; j < 4; j++) s[nt][j] = 0.f;
#pragma unroll
        for (int kk = 0; kk < 16; kk++) {
            u32 A[4], B[4];
            LDSM4(A, qa + kk * 32);
            LDSM4(B, kbase + kk * 32);
            mma_f16(s[0], A[0], A[1], A[2], A[3], B[0], B[2]);
            mma_f16(s[1], A[0], A[1], A[2], A[3], B[1], B[3]);
        }

        // ---- mask + exp + store P + row-sum partials ----
        const int rem = use - c0;   // >= 1
        const int row = mw * 16 + t4;
        float rs_lo = 0.f, rs_hi = 0.f;
#pragma unroll
        for (int nt = 0; nt < 2; nt++) {
            int col = nh * 16 + nt * 8 + 2 * tq;
            float p0 = (col     < rem) ? __expf(s[nt][0]) : 0.f;
            float p1 = (col + 1 < rem) ? __expf(s[nt][1]) : 0.f;
            float p2 = (col     < rem) ? __expf(s[nt][2]) : 0.f;
            float p3 = (col + 1 < rem) ? __expf(s[nt][3]) : 0.f;
            rs_lo += p0 + p1;
            rs_hi += p2 + p3;
            *(u32*)(Ps + row * PSTR + col)       = packh2(p0, p1);
            *(u32*)(Ps + (row + 8) * PSTR + col) = packh2(p2, p3);
        }
        rs_lo += __shfl_xor_sync(0xffffffffu, rs_lo, 1);
        rs_lo += __shfl_xor_sync(0xffffffffu, rs_lo, 2);
        rs_hi += __shfl_xor_sync(0xffffffffu, rs_hi, 1);
        rs_hi += __shfl_xor_sync(0xffffffffu, rs_hi, 2);
        if (tq == 0) {   // unique writer per (row, key-half)
            if (ch == 0) {
                Ls[row * 2 + nh]       = rs_lo;
                Ls[(row + 8) * 2 + nh] = rs_hi;
            } else {
                Ls[row * 2 + nh]       += rs_lo;
                Ls[(row + 8) * 2 + nh] += rs_hi;
            }
        }
        __syncthreads();   // C: P + Ls visible

        // ---- acc += P @ V : m32 x n64 over k=32 ----
        const u32 vbase = vt_u + buf * VBUF * 2 + vb0;
#pragma unroll
        for (int kk = 0; kk < 2; kk++) {
            u32 A0[4], A1[4];
            LDSM4(A0, pa0 + kk * 32);
            LDSM4(A1, pa1 + kk * 32);
#pragma unroll
            for (int nt = 0; nt < 4; nt++) {
                u32 B[4];
                LDSM4(B, vbase + nt * 16 * VSTR * 2 + kk * 32);
                mma_f16(acc[0][2 * nt],     A0[0], A0[1], A0[2], A0[3], B[0], B[2]);
                mma_f16(acc[0][2 * nt + 1], A0[0], A0[1], A0[2], A0[3], B[1], B[3]);
                mma_f16(acc[1][2 * nt],     A1[0], A1[1], A1[2], A1[3], B[0], B[2]);
                mma_f16(acc[1][2 * nt + 1], A1[0], A1[1], A1[2], A1[3], B[1], B[3]);
            }
        }
    }

    // ---- finalize: write acc / rowsum as fp16 partial for this block ----
    __half* dst = g_r + (size_t)b * NQ * DK;
#pragma unroll
    for (int mt = 0; mt < 2; mt++) {
        int r = mg * 32 + mt * 16 + t4;
        float il = 1.0f / (Ls[r * 2] + Ls[r * 2 + 1]);
        float ih = 1.0f / (Ls[(r + 8) * 2] + Ls[(r + 8) * 2 + 1]);
#pragma unroll
        for (int nt = 0; nt < 8; nt++) {
            int col = ng * 64 + nt * 8 + 2 * tq;
            *(u32*)(dst + (size_t)(q0 + r) * DK + col) =
                packh2(acc[mt][nt][0] * il, acc[mt][nt][1] * il);
            *(u32*)(dst + (size_t)(q0 + r + 8) * DK + col) =
                packh2(acc[mt][nt][2] * ih, acc[mt][nt][3] * ih);
        }
    }
}

// ---------------------------------------------------------------------------
// Kernel R: reduce 32 fp16 partials -> g_rsh (fp16)
// ---------------------------------------------------------------------------
__global__ __launch_bounds__(256) void reduce_r_kernel()
{
    size_t i = ((size_t)blockIdx.x * 256 + threadIdx.x) * 8;
    float a[8];
#pragma unroll
    for (int j = 0; j < 8; j++) a[j] = 0.f;
#pragma unroll
    for (int p = 0; p < NPART; p++) {
        uint4 v = *(const uint4*)(g_r + (size_t)p * NQ * DK + i);
        const __half2* h = (const __half2*)&v;
#pragma unroll
        for (int j = 0; j < 4; j++) {
            float2 f = __half22float2(h[j]);
            a[2 * j] += f.x; a[2 * j + 1] += f.y;
        }
    }
    *(uint4*)(g_rsh + i) = make_uint4(packh2(a[0], a[1]), packh2(a[2], a[3]),
                                      packh2(a[4], a[5]), packh2(a[6], a[7]));
}

// ---------------------------------------------------------------------------
// Kernel C: out = g_rsh @ WoT^T + bo   fp16 tensor-core GEMM, 2 CTAs/SM.
// ---------------------------------------------------------------------------
#define OG_ASTR 264
#define OG_SMEM (64 * OG_ASTR * 2 + 128 * OG_ASTR * 2)

extern __shared__ char og_raw[];

__global__ void __launch_bounds__(256, 2) out_gemm_kernel(
    const float* __restrict__ bo, float* __restrict__ out)
{
    __half* As = (__half*)og_raw;
    __half* Bs = As + 64 * OG_ASTR;

    const int tid = threadIdx.x;
    const int w = tid >> 5, lane = tid & 31;
    const int t4 = lane >> 2, tq = lane & 3;
    const int mw = w & 3, nh = w >> 2;
    const int m0 = blockIdx.x * 64;
    const int n0 = blockIdx.y * 128;

    const int l15 = lane & 15, lh = lane >> 4;
    const u32 qa = s2u(As) + (u32)(((mw * 16 + l15) * OG_ASTR + lh * 8) * 2);
    const u32 qb = s2u(Bs) + (u32)(((nh * 64 + l15) * OG_ASTR + lh * 8) * 2);

#pragma unroll
    for (int u = 0; u < 8; u++) {
        int idx = tid + u * 256;
        int row = idx >> 5, seg = idx & 31;
        *(uint4*)(As + row * OG_ASTR + seg * 8) =
            *(const uint4*)(g_rsh + (size_t)(m0 + row) * DK + seg * 8);
    }
#pragma unroll
    for (int u = 0; u < 16; u++) {
        int idx = tid + u * 256;
        int row = idx >> 5, seg = idx & 31;
        *(uint4*)(Bs + row * OG_ASTR + seg * 8) =
            *(const uint4*)(g_woth + (size_t)(n0 + row) * DK + seg * 8);
    }
    __syncthreads();

    float acc[8][4];
#pragma unroll
    for (int nt = 0; nt < 8; nt++)
#pragma unroll
        for (int j = 0; j < 4; j++) acc[nt][j] = 0.f;

#pragma unroll
    for (int kk = 0; kk < 16; kk++) {
        u32 A[4];
        LDSM4(A, qa + kk * 32);
#pragma unroll
        for (int nt16 = 0; nt16 < 4; nt16++) {
            u32 B[4];
            LDSM4(B, qb + nt16 * 16 * OG_ASTR * 2 + kk * 32);
            mma_f16(acc[2 * nt16],     A[0], A[1], A[2], A[3], B[0], B[2]);
            mma_f16(acc[2 * nt16 + 1], A[0], A[1], A[2], A[3], B[1], B[3]);
        }
    }

    const int row = m0 + mw * 16 + t4;
#pragma unroll
    for (int nt = 0; nt < 8; nt++) {
        int col = n0 + nh * 64 + nt * 8 + 2 * tq;
        float2 bv = *(const float2*)(bo + col);
        *(float2*)(out + (size_t)row * DH + col) =
            make_float2(acc[nt][0] + bv.x, acc[nt][1] + bv.y);
        *(float2*)(out + (size_t)(row + 8) * DH + col) =
            make_float2(acc[nt][2] + bv.x, acc[nt][3] + bv.y);
    }
}

// ---------------------------------------------------------------------------
extern "C" void kernel_launch(void* const* d_in, const int* in_sizes, int n_in,
                              void* d_out, int out_size)
{
    const float* hs  = (const float*)d_in[0];
    const float* Wk  = (const float*)d_in[1];
    const float* bk  = (const float*)d_in[2];
    const float* lnw = (const float*)d_in[3];
    const float* lnb = (const float*)d_in[4];
    const float* mk  = (const float*)d_in[5];
    const float* mv  = (const float*)d_in[6];
    const float* Wo  = (const float*)d_in[7];
    const float* bo  = (const float*)d_in[8];
    const int* usage = (const int*)d_in[9];
    float* out = (float*)d_out;

    cudaFuncSetAttribute(attn_kernel, cudaFuncAttributeMaxDynamicSharedMemorySize,
                         ATTN_SMEM);
    cudaFuncSetAttribute(qproj_ln_kernel, cudaFuncAttributeMaxDynamicSharedMemorySize,
                         QP_SMEM);
    cudaFuncSetAttribute(out_gemm_kernel, cudaFuncAttributeMaxDynamicSharedMemorySize,
                         OG_SMEM);

    prep_kernel<<<PREP_GRID, 256>>>(mk, mv, hs, Wk, Wo);
    qproj_ln_kernel<<<NQ / 32, 256, QP_SMEM>>>(bk, lnw, lnb);
    attn_kernel<<<dim3(NQ / 64, NPART), 256, ATTN_SMEM>>>(usage);
    reduce_r_kernel<<<(NQ * DK) / (256 * 8), 256>>>();
    out_gemm_kernel<<<dim3(NQ / 64, DH / 128), 256, OG_SMEM>>>(bo, out);
}